// round 7
// baseline (speedup 1.0000x reference)
#include <cuda_runtime.h>
#include <cuda_bf16.h>
#include <cstdint>

typedef __nv_bfloat16 bf16;

// ===========================================================================
// out = 2048 * x @ (Wv @ Wo) + (2048 * bv @ Wo + bo)
// (softmax rows sum to 1; einsum 'bvhd,bhqk->bvhd' has no shared contraction
//  index -> attention collapses to scalar 2048)
//
// mma.sync.m16n8k16 bf16 with fp32 operands pre-split into bf16 hi/lo global
// arrays (tiled [K/32][rows][40] to match smem layout), moved by cp.async.cg
// (L1 bypass). 3-term MMA (AhBh + AhBl + AlBh) -> ~1e-5 relative accuracy.
// R7: L1/smem-bandwidth was the limiter (81%): pre-split + cp.async removes
// the LDG/convert/STS path; GEMM2 warp tile 64x32 cuts ldsm bytes/MMA 25%.
// ===========================================================================

__device__ bf16 g_xh[32u * 8192u * 40u];
__device__ bf16 g_xl[32u * 8192u * 40u];
__device__ bf16 g_wvh[32u * 1024u * 40u];
__device__ bf16 g_wvl[32u * 1024u * 40u];
__device__ bf16 g_woth[32u * 1024u * 40u];
__device__ bf16 g_wotl[32u * 1024u * 40u];
__device__ bf16 g_wch[32u * 1024u * 40u];
__device__ bf16 g_wcl[32u * 1024u * 40u];
__device__ float g_c[1024];

__device__ __forceinline__ uint32_t smem_u32(const void* p) {
    uint32_t a;
    asm("{ .reg .u64 t; cvta.to.shared.u64 t, %1; cvt.u32.u64 %0, t; }"
        : "=r"(a) : "l"(p));
    return a;
}

__device__ __forceinline__ void ldsm4(uint32_t* r, uint32_t addr) {
    asm volatile("ldmatrix.sync.aligned.m8n8.x4.shared.b16 {%0,%1,%2,%3}, [%4];"
                 : "=r"(r[0]), "=r"(r[1]), "=r"(r[2]), "=r"(r[3]) : "r"(addr));
}

__device__ __forceinline__ void mma16816(float* c, const uint32_t* a, const uint32_t* b) {
    asm volatile(
        "mma.sync.aligned.m16n8k16.row.col.f32.bf16.bf16.f32 "
        "{%0,%1,%2,%3}, {%4,%5,%6,%7}, {%8,%9}, {%0,%1,%2,%3};"
        : "+f"(c[0]), "+f"(c[1]), "+f"(c[2]), "+f"(c[3])
        : "r"(a[0]), "r"(a[1]), "r"(a[2]), "r"(a[3]), "r"(b[0]), "r"(b[1]));
}

__device__ __forceinline__ void cpa16(uint32_t s, const void* g) {
    asm volatile("cp.async.cg.shared.global [%0], [%1], 16;" :: "r"(s), "l"(g) : "memory");
}

// pack two fp32 -> bf16x2 hi and lo
__device__ __forceinline__ void split2(float a, float b, uint32_t& h, uint32_t& l) {
    __nv_bfloat16 ha = __float2bfloat16_rn(a), hb = __float2bfloat16_rn(b);
    __nv_bfloat16 la = __float2bfloat16_rn(a - __bfloat162float(ha));
    __nv_bfloat16 lb = __float2bfloat16_rn(b - __bfloat162float(hb));
    __nv_bfloat162 hp = __halves2bfloat162(ha, hb);
    __nv_bfloat162 lp = __halves2bfloat162(la, lb);
    h = *reinterpret_cast<uint32_t*>(&hp);
    l = *reinterpret_cast<uint32_t*>(&lp);
}

// ---------------------------------------------------------------------------
// split fp32 [M][1024] row-major -> tiled bf16 hi/lo [kc=k>>5][M][40]
// (only first 32 of each 40-elem row used; stride 40 = 80 B matches smem)
// ---------------------------------------------------------------------------
__global__ void split_tiled(const float* __restrict__ in, bf16* __restrict__ oh,
                            bf16* __restrict__ ol, int M)
{
    const int idx = blockIdx.x * 256 + threadIdx.x;   // one float4 per thread
    const int row = idx >> 8;
    const int k = (idx & 255) * 4;
    const float4 v = *reinterpret_cast<const float4*>(in + (size_t)row * 1024 + k);
    const size_t o = ((size_t)(k >> 5) * M + row) * 40 + (k & 31);
    uint2 hp, lp;
    split2(v.x, v.y, hp.x, lp.x);
    split2(v.z, v.w, hp.y, lp.y);
    *reinterpret_cast<uint2*>(oh + o) = hp;
    *reinterpret_cast<uint2*>(ol + o) = lp;
}

// ---------------------------------------------------------------------------
// Wo [m=1024][o=1024] -> transpose+split: oh/ol [kc=m>>5][o][m&31]
// ---------------------------------------------------------------------------
__global__ void transpose_split(const float* __restrict__ Wo,
                                bf16* __restrict__ oh, bf16* __restrict__ ol)
{
    __shared__ float t[32][33];
    const int bo = blockIdx.x * 32;   // o block
    const int bm = blockIdx.y * 32;   // m block (= one kc chunk)
    const int tx = threadIdx.x, ty = threadIdx.y;   // block 32x8
    #pragma unroll
    for (int i = 0; i < 32; i += 8)
        t[ty + i][tx] = Wo[(size_t)(bm + ty + i) * 1024 + bo + tx];
    __syncthreads();
    const int tid = ty * 32 + tx;
    const int oo = tid >> 3;          // local o (0..31)
    const int ml = (tid & 7) * 4;     // local m quad
    const size_t o = ((size_t)blockIdx.y * 1024 + bo + oo) * 40 + ml;
    uint2 hp, lp;
    split2(t[ml + 0][oo], t[ml + 1][oo], hp.x, lp.x);
    split2(t[ml + 2][oo], t[ml + 3][oo], hp.y, lp.y);
    *reinterpret_cast<uint2*>(oh + o) = hp;
    *reinterpret_cast<uint2*>(ol + o) = lp;
}

// ---------------------------------------------------------------------------
// c[j] = 2048 * sum_k bv[k]*Wo[k][j] + bo[j]
// ---------------------------------------------------------------------------
__global__ void bias_fold_kernel(const float* __restrict__ bv,
                                 const float* __restrict__ Wo,
                                 const float* __restrict__ bo,
                                 float* __restrict__ c)
{
    __shared__ float red[256];
    const int j = blockIdx.x;
    float s = 0.0f;
    #pragma unroll 4
    for (int k = threadIdx.x; k < 1024; k += 256)
        s += bv[k] * Wo[k * 1024 + j];
    red[threadIdx.x] = s;
    __syncthreads();
    #pragma unroll
    for (int off = 128; off > 0; off >>= 1) {
        if (threadIdx.x < off) red[threadIdx.x] += red[threadIdx.x + off];
        __syncthreads();
    }
    if (threadIdx.x == 0) c[j] = 2048.0f * red[0] + bo[j];
}

// ---------------------------------------------------------------------------
// GEMM: C[M,N] = alpha * A @ B^T + bias, operands pre-split bf16 hi/lo tiled
// [kc][rows][40]. CTA tile BM x BN, BK=32, 256 threads, warp tile WM x WN.
// EPI=0: fp32 out (alpha, bias). EPI=1: write C split-bf16 tiled (for GEMM2 B).
// 2-stage cp.async.cg pipeline.
// ---------------------------------------------------------------------------
template <int BM, int BN, int WM, int WN, int EPI>
__global__ void __launch_bounds__(256, 2)
gemm_bf16(const bf16* __restrict__ Ah, const bf16* __restrict__ Al,
          const bf16* __restrict__ Bh, const bf16* __restrict__ Bl,
          float* __restrict__ Cf, bf16* __restrict__ Ch, bf16* __restrict__ Cl,
          int M, int N, int K, float alpha, const float* __restrict__ bias)
{
    constexpr int WARPS_N = BN / WN;
    constexpr int MT  = WM / 16;
    constexpr int NTT = WN / 8;
    constexpr int NP  = WN / 16;
    constexpr int A_CH = BM * 4 / 256;   // 16B chunks per thread for A (per matrix)
    constexpr int B_CH = BN * 4 / 256;
    constexpr uint32_t OFF_AL = (uint32_t)BM * 80u;
    constexpr uint32_t OFF_BH = 2u * BM * 80u;
    constexpr uint32_t OFF_BL = 2u * BM * 80u + (uint32_t)BN * 80u;
    constexpr uint32_t STAGE  = 2u * (BM + BN) * 80u;

    extern __shared__ __align__(128) char smem_raw[];
    const uint32_t sb = smem_u32(smem_raw);

    const int tid = threadIdx.x;
    const int wid = tid >> 5;
    const int lane = tid & 31;
    const int warp_m = wid / WARPS_N;
    const int warp_n = wid % WARPS_N;
    const int row0 = blockIdx.y * BM;
    const int col0 = blockIdx.x * BN;

    const uint32_t aoff = (uint32_t)((warp_m * WM + (lane & 7) + ((lane >> 3) & 1) * 8) * 80
                                     + (lane >> 4) * 16);
    const uint32_t boff = (uint32_t)((warp_n * WN + (lane & 7) + ((lane >> 4) & 1) * 8) * 80
                                     + ((lane >> 3) & 1) * 16);

    float acc[MT][NTT][4] = {};

    const int NT = K >> 5;
    const int cr = tid >> 2, cc = (tid & 3) * 16;   // copy row / byte col

    auto issue = [&](int kt, int s) {
        const uint32_t ds = sb + (uint32_t)s * STAGE;
        const size_t ga = ((size_t)kt * M + row0 + cr) * 80 + cc;
        #pragma unroll
        for (int j = 0; j < A_CH; j++) {
            const size_t g = ga + (size_t)j * 64 * 80;
            const uint32_t d = ds + (uint32_t)(cr + j * 64) * 80 + cc;
            cpa16(d,          (const char*)Ah + g);
            cpa16(d + OFF_AL, (const char*)Al + g);
        }
        const size_t gb = ((size_t)kt * N + col0 + cr) * 80 + cc;
        #pragma unroll
        for (int j = 0; j < B_CH; j++) {
            const size_t g = gb + (size_t)j * 64 * 80;
            const uint32_t d = ds + OFF_BH + (uint32_t)(cr + j * 64) * 80 + cc;
            cpa16(d,                     (const char*)Bh + g);
            cpa16(d + (OFF_BL - OFF_BH), (const char*)Bl + g);
        }
        asm volatile("cp.async.commit_group;" ::: "memory");
    };

    issue(0, 0);

    for (int kt = 0; kt < NT; kt++) {
        const int s = kt & 1;
        asm volatile("cp.async.wait_group 0;" ::: "memory");
        __syncthreads();
        if (kt + 1 < NT) issue(kt + 1, s ^ 1);

        const uint32_t base = sb + (uint32_t)s * STAGE;
        #pragma unroll
        for (int ks = 0; ks < 2; ks++) {
            uint32_t fa[MT][4], fbh[NP][4], fbl[NP][4];
            #pragma unroll
            for (int mt = 0; mt < MT; mt++)
                ldsm4(fa[mt], base + aoff + (uint32_t)(mt * 16 * 80 + ks * 32));
            #pragma unroll
            for (int np = 0; np < NP; np++) {
                const uint32_t bd = base + OFF_BH + boff + (uint32_t)(np * 16 * 80 + ks * 32);
                ldsm4(fbh[np], bd);
                ldsm4(fbl[np], bd + (OFF_BL - OFF_BH));
            }
            // term 1: Ah*Bh
            #pragma unroll
            for (int mt = 0; mt < MT; mt++)
                #pragma unroll
                for (int nt = 0; nt < NTT; nt++)
                    mma16816(acc[mt][nt], fa[mt], &fbh[nt >> 1][(nt & 1) * 2]);
            // term 2: Ah*Bl
            #pragma unroll
            for (int mt = 0; mt < MT; mt++)
                #pragma unroll
                for (int nt = 0; nt < NTT; nt++)
                    mma16816(acc[mt][nt], fa[mt], &fbl[nt >> 1][(nt & 1) * 2]);
            // reload fa <- Al, term 3: Al*Bh
            #pragma unroll
            for (int mt = 0; mt < MT; mt++)
                ldsm4(fa[mt], base + OFF_AL + aoff + (uint32_t)(mt * 16 * 80 + ks * 32));
            #pragma unroll
            for (int mt = 0; mt < MT; mt++)
                #pragma unroll
                for (int nt = 0; nt < NTT; nt++)
                    mma16816(acc[mt][nt], fa[mt], &fbh[nt >> 1][(nt & 1) * 2]);
        }
    }

    // ---- epilogue ----
    const int erow = row0 + warp_m * WM + (lane >> 2);
    const int ecol = col0 + warp_n * WN + (lane & 3) * 2;
    if (EPI == 0) {
        #pragma unroll
        for (int mt = 0; mt < MT; mt++) {
            #pragma unroll
            for (int nt = 0; nt < NTT; nt++) {
                const int cg = ecol + nt * 8;
                const float b0 = bias ? bias[cg]     : 0.0f;
                const float b1 = bias ? bias[cg + 1] : 0.0f;
                float2 v0, v1;
                v0.x = fmaf(alpha, acc[mt][nt][0], b0);
                v0.y = fmaf(alpha, acc[mt][nt][1], b1);
                v1.x = fmaf(alpha, acc[mt][nt][2], b0);
                v1.y = fmaf(alpha, acc[mt][nt][3], b1);
                *reinterpret_cast<float2*>(Cf + (size_t)(erow + mt * 16) * N + cg)     = v0;
                *reinterpret_cast<float2*>(Cf + (size_t)(erow + mt * 16 + 8) * N + cg) = v1;
            }
        }
    } else {
        // write C as tiled split-bf16 [kc=col>>5][row (M total)][col&31]
        #pragma unroll
        for (int mt = 0; mt < MT; mt++) {
            #pragma unroll
            for (int nt = 0; nt < NTT; nt++) {
                const int i0 = ecol + nt * 8;
                const int r0 = erow + mt * 16;
                const size_t o0 = ((size_t)(i0 >> 5) * M + r0) * 40 + (i0 & 31);
                const size_t o1 = o0 + 8 * 40;     // row r0+8
                uint32_t h, l;
                split2(acc[mt][nt][0], acc[mt][nt][1], h, l);
                *reinterpret_cast<uint32_t*>(Ch + o0) = h;
                *reinterpret_cast<uint32_t*>(Cl + o0) = l;
                split2(acc[mt][nt][2], acc[mt][nt][3], h, l);
                *reinterpret_cast<uint32_t*>(Ch + o1) = h;
                *reinterpret_cast<uint32_t*>(Cl + o1) = l;
            }
        }
    }
}

// ---------------------------------------------------------------------------
extern "C" void kernel_launch(void* const* d_in, const int* in_sizes, int n_in,
                              void* d_out, int out_size)
{
    // metadata order: x, encoder_x, Wq, bq, Wk, bk, Wv, bv, Wo, bo
    const float* x  = (const float*)d_in[0];
    const float* Wv = (const float*)d_in[6];
    const float* bv = (const float*)d_in[7];
    const float* Wo = (const float*)d_in[8];
    const float* bo = (const float*)d_in[9];
    float* out = (float*)d_out;

    bf16 *xh, *xl, *wvh, *wvl, *woth, *wotl, *wch, *wcl;
    float* c;
    cudaGetSymbolAddress((void**)&xh,   g_xh);
    cudaGetSymbolAddress((void**)&xl,   g_xl);
    cudaGetSymbolAddress((void**)&wvh,  g_wvh);
    cudaGetSymbolAddress((void**)&wvl,  g_wvl);
    cudaGetSymbolAddress((void**)&woth, g_woth);
    cudaGetSymbolAddress((void**)&wotl, g_wotl);
    cudaGetSymbolAddress((void**)&wch,  g_wch);
    cudaGetSymbolAddress((void**)&wcl,  g_wcl);
    cudaGetSymbolAddress((void**)&c,    g_c);

    constexpr uint32_t SMEM1 = 2u * 2u * (128 + 64)  * 80u;   // 61440
    constexpr uint32_t SMEM2 = 2u * 2u * (128 + 128) * 80u;   // 81920
    cudaFuncSetAttribute((const void*)gemm_bf16<128, 64, 32, 32, 1>,
                         cudaFuncAttributeMaxDynamicSharedMemorySize, (int)SMEM1);
    cudaFuncSetAttribute((const void*)gemm_bf16<128, 128, 64, 32, 0>,
                         cudaFuncAttributeMaxDynamicSharedMemorySize, (int)SMEM2);

    // 0) pre-split operands (x, Wv straight; Wo transposed)
    split_tiled<<<8192, 256>>>(x,  xh,  xl,  8192);
    split_tiled<<<1024, 256>>>(Wv, wvh, wvl, 1024);
    transpose_split<<<dim3(32, 32), dim3(32, 8)>>>(Wo, woth, wotl);
    // 1) c = 2048 * bv @ Wo + bo
    bias_fold_kernel<<<1024, 256>>>(bv, Wo, bo, c);
    // 2) WcT[o,i] = sum_m Wot[o,m]*Wv[i,m] -> split-bf16 tiled (GEMM2's B)
    gemm_bf16<128, 64, 32, 32, 1><<<dim3(16, 8), 256, SMEM1>>>(
        woth, wotl, wvh, wvl, nullptr, wch, wcl, 1024, 1024, 1024, 1.0f, nullptr);
    // 3) out = 2048 * x @ WcT^T + c
    gemm_bf16<128, 128, 64, 32, 0><<<dim3(8, 64), 256, SMEM2>>>(
        xh, xl, wch, wcl, out, nullptr, nullptr, 8192, 1024, 1024, 2048.0f, c);

    (void)in_sizes; (void)n_in; (void)out_size;
}